// round 11
// baseline (speedup 1.0000x reference)
#include <cuda_runtime.h>
#include <cuda_bf16.h>

// EquivariantLayer: edge attention (4 heads), scatter-mean, out-proj, LN, SiLU.
// R11: setup restructured — precompute lives in 2 dedicated blocks (0,1) with
// FULL unroll (R10's unroll-8 cap serialized block-0 and regressed setup to
// 13.9us), while blocks >=2 do the pure zero+pack stream. Kernel duration is
// now max(precompute, pack) instead of their sum. Edge/node unchanged.

#define N_NODES_MAX 100000
#define HEADS 4
#define HIDDEN 32
#define PROJ 128
#define EPT 4   // edges per thread
#define PRE_BLOCKS 2

// ---------------- device scratch (no allocations allowed) ----------------
__device__ float4 g_acc[N_NODES_MAX * HEADS];   // {attn_sum, S.x, S.y, S.z}
__device__ float4 g_pos4[N_NODES_MAX];          // packed positions {x,y,z,0}

struct Pre {
    float G[HEADS][3][3];    // (Wq_h Wk_h^T)/sqrt(32)            36 floats
    float u[HEADS][3];       // (Wq_h bk_h + Wk_h bq_h)/sqrt(32)  12
    float c[HEADS];          // (bq_h . bk_h)/sqrt(32)             4
    float M[HEADS][3][32];   // Wv[c, h-slice] @ Wout[h-slice, j] 384
    float Bw[HEADS][32];     // bv[h-slice] @ Wout[h-slice, j]    128
};
__device__ Pre g_pre;        // 564 floats: G | u | c | M | Bw
__device__ int g_is64;

__device__ __forceinline__ void compute_M(int i, const float* __restrict__ Wv,
                                          const float* __restrict__ Wout) {
    int h = i / 96, rem = i % 96, cd = rem / 32, j = rem % 32;
    float s = 0.f;
    #pragma unroll
    for (int d = 0; d < 32; d++)
        s += Wv[cd * PROJ + h * 32 + d] * Wout[(h * 32 + d) * 32 + j];
    g_pre.M[h][cd][j] = s;
}

// ---------------- 1) setup: blocks 0-1 precompute, blocks >=2 zero+pack -----
__global__ void __launch_bounds__(256) setup_kernel(
        const float* __restrict__ pos, const void* __restrict__ eidx,
        const float* __restrict__ Wq, const float* __restrict__ bq,
        const float* __restrict__ Wk, const float* __restrict__ bk,
        const float* __restrict__ Wv, const float* __restrict__ bv,
        const float* __restrict__ Wout, int N) {
    int b = blockIdx.x;
    int t = threadIdx.x;

    if (b >= PRE_BLOCKS) {
        // ---- streaming blocks: zero accumulators + pack positions ----
        int g = (b - PRE_BLOCKS) * 256 + t;

        if (g < N) {
            float4 z = make_float4(0.f, 0.f, 0.f, 0.f);
            float4* a = &g_acc[(long long)g * 4];
            a[0] = z; a[1] = z; a[2] = z; a[3] = z;
        }

        int quads = N >> 2;
        if (g < quads) {
            const float4* p4 = (const float4*)pos;
            float4 A = p4[3 * g + 0];
            float4 B = p4[3 * g + 1];
            float4 C = p4[3 * g + 2];
            float4* dst = &g_pos4[(long long)g * 4];
            dst[0] = make_float4(A.x, A.y, A.z, 0.f);
            dst[1] = make_float4(A.w, B.x, B.y, 0.f);
            dst[2] = make_float4(B.z, B.w, C.x, 0.f);
            dst[3] = make_float4(C.y, C.z, C.w, 0.f);
        }
        int tail0 = quads * 4;   // tail (none for N=100000)
        if (g >= quads && g < quads + (N - tail0)) {
            int n = tail0 + (g - quads);
            g_pos4[n] = make_float4(pos[3 * n], pos[3 * n + 1], pos[3 * n + 2], 0.f);
        }
        return;
    }

    const float SCALE = 0.17677669529663687f;  // 1/sqrt(32)

    if (b == 0) {
        // M outputs 0..255 (one per thread, full unroll -> 32 loads in flight)
        compute_M(t, Wv, Wout);

        // G/u/c (52 small dots) on threads 0..51
        if (t < 36) {       // G[h][a][b]
            int h = t / 9, rem = t % 9, a = rem / 3, bb = rem % 3;
            float s = 0.f;
            #pragma unroll
            for (int d = 0; d < 32; d++)
                s += Wq[a * PROJ + h * 32 + d] * Wk[bb * PROJ + h * 32 + d];
            g_pre.G[h][a][bb] = s * SCALE;
        } else if (t < 48) { // u[h][a]
            int i = t - 36, h = i / 3, a = i % 3;
            float s = 0.f;
            #pragma unroll
            for (int d = 0; d < 32; d++)
                s += Wq[a * PROJ + h * 32 + d] * bk[h * 32 + d]
                   + Wk[a * PROJ + h * 32 + d] * bq[h * 32 + d];
            g_pre.u[h][a] = s * SCALE;
        } else if (t < 52) { // c[h]
            int h = t - 48;
            float s = 0.f;
            #pragma unroll
            for (int d = 0; d < 32; d++)
                s += bq[h * 32 + d] * bk[h * 32 + d];
            g_pre.c[h] = s * SCALE;
        }

        // dtype detect (warp 2, t in [64,96)): int64 in [0,1e5) -> hi-words zero
        if (t >= 64 && t < 96) {
            int l = t - 64;
            const unsigned int* p = (const unsigned int*)eidx;
            bool hz = (p[2 * l + 1] == 0u);
            unsigned int mask = __ballot_sync(0xffffffffu, hz);
            if (l == 0) g_is64 = (mask == 0xffffffffu) ? 1 : 0;
        }
    } else {
        // block 1: M outputs 256..383 on t<128, Bw on t in [128,256)
        if (t < 128) {
            compute_M(256 + t, Wv, Wout);
        } else {
            int i = t - 128, h = i / 32, j = i % 32;   // Bw[h][j]
            float s = 0.f;
            #pragma unroll
            for (int d = 0; d < 32; d++)
                s += bv[h * 32 + d] * Wout[(h * 32 + d) * 32 + j];
            g_pre.Bw[h][j] = s;
        }
    }
}

// ---------------- 2) per-edge: scores -> softmax -> red.v4 scatter ----------
__device__ __forceinline__ void edge_body(const float* sP, int c, float x, float y, float z) {
    float s[HEADS];
    float m = -1e30f;
    #pragma unroll
    for (int h = 0; h < HEADS; h++) {
        const float* G = &sP[h * 9];
        float gx = G[0] * x + G[1] * y + G[2] * z;
        float gy = G[3] * x + G[4] * y + G[5] * z;
        float gz = G[6] * x + G[7] * y + G[8] * z;
        float v = x * gx + y * gy + z * gz
                + sP[36 + h * 3 + 0] * x + sP[36 + h * 3 + 1] * y + sP[36 + h * 3 + 2] * z
                + sP[48 + h];
        s[h] = v;
        m = fmaxf(m, v);
    }
    float tsum = 0.f;
    #pragma unroll
    for (int h = 0; h < HEADS; h++) { s[h] = __expf(s[h] - m); tsum += s[h]; }
    float inv = 1.0f / tsum;

    float4* base = &g_acc[(long long)c * HEADS];
    #pragma unroll
    for (int h = 0; h < HEADS; h++) {
        float a = s[h] * inv;
        float4* p = base + h;
        asm volatile("red.global.add.v4.f32 [%0], {%1, %2, %3, %4};"
                     :: "l"(p), "f"(a), "f"(a * x), "f"(a * y), "f"(a * z)
                     : "memory");
    }
}

__global__ void __launch_bounds__(256) edge_kernel(const void* __restrict__ eidx, int E) {
    __shared__ float sP[52];  // [0:36) G, [36:48) u, [48:52) c
    int t = threadIdx.x;
    if (t < 52) sP[t] = ((const float*)&g_pre)[t];
    __syncthreads();

    int e0 = (blockIdx.x * 256 + t) * EPT;
    if (e0 >= E) return;
    int is64 = g_is64;
    int nleft = E - e0;

    if (nleft >= EPT) {
        int r[EPT], c[EPT];
        if (is64) {
            const long long* p = (const long long*)eidx;
            if (((unsigned)E & 1u) == 0u) {   // e0 is always even
                longlong2 A = *(const longlong2*)(p + e0);
                longlong2 B = *(const longlong2*)(p + e0 + 2);
                longlong2 C = *(const longlong2*)(p + E + e0);
                longlong2 D = *(const longlong2*)(p + E + e0 + 2);
                r[0] = (int)A.x; r[1] = (int)A.y; r[2] = (int)B.x; r[3] = (int)B.y;
                c[0] = (int)C.x; c[1] = (int)C.y; c[2] = (int)D.x; c[3] = (int)D.y;
            } else {
                #pragma unroll
                for (int i = 0; i < EPT; i++) {
                    r[i] = (int)p[e0 + i];
                    c[i] = (int)p[(long long)E + e0 + i];
                }
            }
        } else {
            const int* p = (const int*)eidx;
            if (((unsigned)E & 3u) == 0u) {   // e0 is always a multiple of 4
                int4 A = *(const int4*)(p + e0);
                int4 C = *(const int4*)(p + E + e0);
                r[0] = A.x; r[1] = A.y; r[2] = A.z; r[3] = A.w;
                c[0] = C.x; c[1] = C.y; c[2] = C.z; c[3] = C.w;
            } else {
                #pragma unroll
                for (int i = 0; i < EPT; i++) { r[i] = p[e0 + i]; c[i] = p[E + e0 + i]; }
            }
        }

        // batch the 8 gathers for maximum MLP before any compute
        float4 Pr[EPT], Pc[EPT];
        #pragma unroll
        for (int i = 0; i < EPT; i++) Pr[i] = __ldg(&g_pos4[r[i]]);
        #pragma unroll
        for (int i = 0; i < EPT; i++) Pc[i] = __ldg(&g_pos4[c[i]]);

        #pragma unroll
        for (int i = 0; i < EPT; i++)
            edge_body(sP, c[i], Pr[i].x - Pc[i].x, Pr[i].y - Pc[i].y, Pr[i].z - Pc[i].z);
    } else {
        for (int i = 0; i < nleft; i++) {
            int r, c;
            if (is64) {
                const long long* p = (const long long*)eidx;
                r = (int)p[e0 + i];
                c = (int)p[(long long)E + e0 + i];
            } else {
                const int* p = (const int*)eidx;
                r = p[e0 + i];
                c = p[E + e0 + i];
            }
            float4 Pr = __ldg(&g_pos4[r]);
            float4 Pc = __ldg(&g_pos4[c]);
            edge_body(sP, c, Pr.x - Pc.x, Pr.y - Pc.y, Pr.z - Pc.z);
        }
    }
}

// ---------------- 3) per-node: reconstruct, project, LN, SiLU ----------------
__global__ void __launch_bounds__(256) node_kernel(float* __restrict__ out,
                                                   const float* __restrict__ bout,
                                                   const float* __restrict__ gamma,
                                                   const float* __restrict__ beta, int N) {
    __shared__ float sM[512];   // M (384) then Bw (128)
    __shared__ float sB[96];    // bout | gamma | beta
    const float* src = ((const float*)&g_pre) + 52;
    for (int i = threadIdx.x; i < 512; i += blockDim.x) sM[i] = src[i];
    if (threadIdx.x < 32) {
        sB[threadIdx.x]      = bout[threadIdx.x];
        sB[32 + threadIdx.x] = gamma[threadIdx.x];
        sB[64 + threadIdx.x] = beta[threadIdx.x];
    }
    __syncthreads();

    int n = (blockIdx.x * blockDim.x + threadIdx.x) >> 5;
    int j = threadIdx.x & 31;
    if (n >= N) return;

    float4 a0 = g_acc[n * 4 + 0];
    float4 a1 = g_acc[n * 4 + 1];
    float4 a2 = g_acc[n * 4 + 2];
    float4 a3 = g_acc[n * 4 + 3];

    float cnt = a0.x + a1.x + a2.x + a3.x;   // == edge count (softmax sums to 1)
    float inv = 1.0f / fmaxf(cnt, 1.0f);

    float acc =
        a0.y * sM[  0 + j] + a0.z * sM[ 32 + j] + a0.w * sM[ 64 + j] + a0.x * sM[384 + j] +
        a1.y * sM[ 96 + j] + a1.z * sM[128 + j] + a1.w * sM[160 + j] + a1.x * sM[416 + j] +
        a2.y * sM[192 + j] + a2.z * sM[224 + j] + a2.w * sM[256 + j] + a2.x * sM[448 + j] +
        a3.y * sM[288 + j] + a3.z * sM[320 + j] + a3.w * sM[352 + j] + a3.x * sM[480 + j];

    float o = acc * inv + sB[j];

    float mu = o;
    #pragma unroll
    for (int off = 16; off > 0; off >>= 1) mu += __shfl_xor_sync(0xffffffffu, mu, off);
    mu *= (1.0f / 32.0f);
    float d = o - mu;
    float var = d * d;
    #pragma unroll
    for (int off = 16; off > 0; off >>= 1) var += __shfl_xor_sync(0xffffffffu, var, off);
    var *= (1.0f / 32.0f);

    float yv = d * rsqrtf(var + 1e-5f) * sB[32 + j] + sB[64 + j];
    out[(long long)n * 32 + j] = yv / (1.0f + __expf(-yv));   // SiLU
}

// ---------------- launch ----------------
extern "C" void kernel_launch(void* const* d_in, const int* in_sizes, int n_in,
                              void* d_out, int out_size) {
    const float* pos   = (const float*)d_in[0];
    const void*  eidx  = d_in[1];
    const float* Wq    = (const float*)d_in[2];
    const float* bq    = (const float*)d_in[3];
    const float* Wk    = (const float*)d_in[4];
    const float* bk    = (const float*)d_in[5];
    const float* Wv    = (const float*)d_in[6];
    const float* bv    = (const float*)d_in[7];
    const float* Wout  = (const float*)d_in[8];
    const float* bout  = (const float*)d_in[9];
    const float* gamma = (const float*)d_in[10];
    const float* beta  = (const float*)d_in[11];

    int N = in_sizes[0] / 3;      // 100000
    int E = in_sizes[1] / 2;      // 500000
    if (N > N_NODES_MAX) N = N_NODES_MAX;

    int packBlocks = (N + 255) / 256;
    setup_kernel<<<packBlocks + PRE_BLOCKS, 256>>>(pos, eidx, Wq, bq, Wk, bk, Wv, bv, Wout, N);
    edge_kernel<<<(E + 256 * EPT - 1) / (256 * EPT), 256>>>(eidx, E);
    node_kernel<<<(N + 7) / 8, 256>>>((float*)d_out, bout, gamma, beta, N);
}

// round 13
// speedup vs baseline: 1.5272x; 1.5272x over previous
#include <cuda_runtime.h>
#include <cuda_bf16.h>

// EquivariantLayer: edge attention (4 heads), scatter-mean, out-proj, LN, SiLU.
// R12: revert to the R7 structure (best measured, 49.6us). Single change:
// g_acc zeroing removed from setup — __device__ globals start zeroed at module
// load, and node_kernel re-zeroes each node's accumulators after consuming
// them, so g_acc is zeroed on entry to EVERY kernel_launch call by induction.
// Deterministic: identical work and output on every call.

#define N_NODES_MAX 100000
#define HEADS 4
#define HIDDEN 32
#define PROJ 128
#define EPT 4   // edges per thread

// ---------------- device scratch (no allocations allowed) ----------------
__device__ float4 g_acc[N_NODES_MAX * HEADS];   // {attn_sum, S.x, S.y, S.z}; zero at load
__device__ float4 g_pos4[N_NODES_MAX];          // packed positions {x,y,z,0}

struct Pre {
    float G[HEADS][3][3];    // (Wq_h Wk_h^T)/sqrt(32)            36 floats
    float u[HEADS][3];       // (Wq_h bk_h + Wk_h bq_h)/sqrt(32)  12
    float c[HEADS];          // (bq_h . bk_h)/sqrt(32)             4
    float M[HEADS][3][32];   // Wv[c, h-slice] @ Wout[h-slice, j] 384
    float Bw[HEADS][32];     // bv[h-slice] @ Wout[h-slice, j]    128
};
__device__ Pre g_pre;        // 564 floats: G | u | c | M | Bw
__device__ int g_is64;

// ---------------- 1) setup: detect + precompute + pos-pack ----------------
__global__ void __launch_bounds__(384) setup_kernel(
        const float* __restrict__ pos, const void* __restrict__ eidx,
        const float* __restrict__ Wq, const float* __restrict__ bq,
        const float* __restrict__ Wk, const float* __restrict__ bk,
        const float* __restrict__ Wv, const float* __restrict__ bv,
        const float* __restrict__ Wout, int N) {
    int g = blockIdx.x * 384 + threadIdx.x;
    if (g < N)
        g_pos4[g] = make_float4(pos[3 * g + 0], pos[3 * g + 1], pos[3 * g + 2], 0.f);

    if (blockIdx.x != 0) return;
    int t = threadIdx.x;

    // dtype detect (warp 0): int64 values in [0,1e5) -> every hi-word zero
    if (t < 32) {
        const unsigned int* p = (const unsigned int*)eidx;
        bool hz = (p[2 * t + 1] == 0u);
        unsigned int mask = __ballot_sync(0xffffffffu, hz);
        if (t == 0) g_is64 = (mask == 0xffffffffu) ? 1 : 0;
    }

    const float SCALE = 0.17677669529663687f;  // 1/sqrt(32)
    {   // M[h][c][j], 384 threads, full unroll for MLP
        int h = t / 96, rem = t % 96, cd = rem / 32, j = rem % 32;
        float s = 0.f;
        #pragma unroll
        for (int d = 0; d < 32; d++)
            s += Wv[cd * PROJ + h * 32 + d] * Wout[(h * 32 + d) * 32 + j];
        g_pre.M[h][cd][j] = s;
    }
    if (t < 128) {  // Bw[h][j]
        int h = t / 32, j = t % 32;
        float s = 0.f;
        #pragma unroll
        for (int d = 0; d < 32; d++)
            s += bv[h * 32 + d] * Wout[(h * 32 + d) * 32 + j];
        g_pre.Bw[h][j] = s;
    }
    if (t < 36) {   // G[h][a][b]
        int h = t / 9, rem = t % 9, a = rem / 3, b = rem % 3;
        float s = 0.f;
        #pragma unroll
        for (int d = 0; d < 32; d++)
            s += Wq[a * PROJ + h * 32 + d] * Wk[b * PROJ + h * 32 + d];
        g_pre.G[h][a][b] = s * SCALE;
    }
    if (t < 12) {   // u[h][a]
        int h = t / 3, a = t % 3;
        float s = 0.f;
        #pragma unroll
        for (int d = 0; d < 32; d++)
            s += Wq[a * PROJ + h * 32 + d] * bk[h * 32 + d]
               + Wk[a * PROJ + h * 32 + d] * bq[h * 32 + d];
        g_pre.u[h][a] = s * SCALE;
    }
    if (t < 4) {    // c[h]
        float s = 0.f;
        #pragma unroll
        for (int d = 0; d < 32; d++)
            s += bq[t * 32 + d] * bk[t * 32 + d];
        g_pre.c[t] = s * SCALE;
    }
}

// ---------------- 2) per-edge: scores -> softmax -> red.v4 scatter ----------
__device__ __forceinline__ void edge_body(const float* sP, int c, float x, float y, float z) {
    float s[HEADS];
    float m = -1e30f;
    #pragma unroll
    for (int h = 0; h < HEADS; h++) {
        const float* G = &sP[h * 9];
        float gx = G[0] * x + G[1] * y + G[2] * z;
        float gy = G[3] * x + G[4] * y + G[5] * z;
        float gz = G[6] * x + G[7] * y + G[8] * z;
        float v = x * gx + y * gy + z * gz
                + sP[36 + h * 3 + 0] * x + sP[36 + h * 3 + 1] * y + sP[36 + h * 3 + 2] * z
                + sP[48 + h];
        s[h] = v;
        m = fmaxf(m, v);
    }
    float tsum = 0.f;
    #pragma unroll
    for (int h = 0; h < HEADS; h++) { s[h] = __expf(s[h] - m); tsum += s[h]; }
    float inv = 1.0f / tsum;

    float4* base = &g_acc[(long long)c * HEADS];
    #pragma unroll
    for (int h = 0; h < HEADS; h++) {
        float a = s[h] * inv;
        float4* p = base + h;
        asm volatile("red.global.add.v4.f32 [%0], {%1, %2, %3, %4};"
                     :: "l"(p), "f"(a), "f"(a * x), "f"(a * y), "f"(a * z)
                     : "memory");
    }
}

__global__ void __launch_bounds__(256) edge_kernel(const void* __restrict__ eidx, int E) {
    __shared__ float sP[52];  // [0:36) G, [36:48) u, [48:52) c
    int t = threadIdx.x;
    if (t < 52) sP[t] = ((const float*)&g_pre)[t];
    __syncthreads();

    int e0 = (blockIdx.x * 256 + t) * EPT;
    if (e0 >= E) return;
    int is64 = g_is64;
    int nleft = E - e0;

    if (nleft >= EPT) {
        int r[EPT], c[EPT];
        if (is64) {
            const long long* p = (const long long*)eidx;
            if (((unsigned)E & 1u) == 0u) {   // e0 is always even
                longlong2 A = *(const longlong2*)(p + e0);
                longlong2 B = *(const longlong2*)(p + e0 + 2);
                longlong2 C = *(const longlong2*)(p + E + e0);
                longlong2 D = *(const longlong2*)(p + E + e0 + 2);
                r[0] = (int)A.x; r[1] = (int)A.y; r[2] = (int)B.x; r[3] = (int)B.y;
                c[0] = (int)C.x; c[1] = (int)C.y; c[2] = (int)D.x; c[3] = (int)D.y;
            } else {
                #pragma unroll
                for (int i = 0; i < EPT; i++) {
                    r[i] = (int)p[e0 + i];
                    c[i] = (int)p[(long long)E + e0 + i];
                }
            }
        } else {
            const int* p = (const int*)eidx;
            if (((unsigned)E & 3u) == 0u) {   // e0 is always a multiple of 4
                int4 A = *(const int4*)(p + e0);
                int4 C = *(const int4*)(p + E + e0);
                r[0] = A.x; r[1] = A.y; r[2] = A.z; r[3] = A.w;
                c[0] = C.x; c[1] = C.y; c[2] = C.z; c[3] = C.w;
            } else {
                #pragma unroll
                for (int i = 0; i < EPT; i++) { r[i] = p[e0 + i]; c[i] = p[E + e0 + i]; }
            }
        }

        // batch the 8 gathers for maximum MLP before any compute
        float4 Pr[EPT], Pc[EPT];
        #pragma unroll
        for (int i = 0; i < EPT; i++) Pr[i] = __ldg(&g_pos4[r[i]]);
        #pragma unroll
        for (int i = 0; i < EPT; i++) Pc[i] = __ldg(&g_pos4[c[i]]);

        #pragma unroll
        for (int i = 0; i < EPT; i++)
            edge_body(sP, c[i], Pr[i].x - Pc[i].x, Pr[i].y - Pc[i].y, Pr[i].z - Pc[i].z);
    } else {
        for (int i = 0; i < nleft; i++) {
            int r, c;
            if (is64) {
                const long long* p = (const long long*)eidx;
                r = (int)p[e0 + i];
                c = (int)p[(long long)E + e0 + i];
            } else {
                const int* p = (const int*)eidx;
                r = p[e0 + i];
                c = p[E + e0 + i];
            }
            float4 Pr = __ldg(&g_pos4[r]);
            float4 Pc = __ldg(&g_pos4[c]);
            edge_body(sP, c, Pr.x - Pc.x, Pr.y - Pc.y, Pr.z - Pc.z);
        }
    }
}

// ---------------- 3) per-node: reconstruct, project, LN, SiLU, re-zero ------
__global__ void __launch_bounds__(256) node_kernel(float* __restrict__ out,
                                                   const float* __restrict__ bout,
                                                   const float* __restrict__ gamma,
                                                   const float* __restrict__ beta, int N) {
    __shared__ float sM[512];   // M (384) then Bw (128)
    __shared__ float sB[96];    // bout | gamma | beta
    const float* src = ((const float*)&g_pre) + 52;
    for (int i = threadIdx.x; i < 512; i += blockDim.x) sM[i] = src[i];
    if (threadIdx.x < 32) {
        sB[threadIdx.x]      = bout[threadIdx.x];
        sB[32 + threadIdx.x] = gamma[threadIdx.x];
        sB[64 + threadIdx.x] = beta[threadIdx.x];
    }
    __syncthreads();

    int n = (blockIdx.x * blockDim.x + threadIdx.x) >> 5;
    int j = threadIdx.x & 31;
    if (n >= N) return;

    float4 a0 = g_acc[n * 4 + 0];
    float4 a1 = g_acc[n * 4 + 1];
    float4 a2 = g_acc[n * 4 + 2];
    float4 a3 = g_acc[n * 4 + 3];

    // re-zero for the next kernel_launch call (lanes 0..3 of this warp cover
    // the node's 4 float4 slots; values already in registers above)
    if (j < 4) g_acc[n * 4 + j] = make_float4(0.f, 0.f, 0.f, 0.f);

    float cnt = a0.x + a1.x + a2.x + a3.x;   // == edge count (softmax sums to 1)
    float inv = 1.0f / fmaxf(cnt, 1.0f);

    float acc =
        a0.y * sM[  0 + j] + a0.z * sM[ 32 + j] + a0.w * sM[ 64 + j] + a0.x * sM[384 + j] +
        a1.y * sM[ 96 + j] + a1.z * sM[128 + j] + a1.w * sM[160 + j] + a1.x * sM[416 + j] +
        a2.y * sM[192 + j] + a2.z * sM[224 + j] + a2.w * sM[256 + j] + a2.x * sM[448 + j] +
        a3.y * sM[288 + j] + a3.z * sM[320 + j] + a3.w * sM[352 + j] + a3.x * sM[480 + j];

    float o = acc * inv + sB[j];

    float mu = o;
    #pragma unroll
    for (int off = 16; off > 0; off >>= 1) mu += __shfl_xor_sync(0xffffffffu, mu, off);
    mu *= (1.0f / 32.0f);
    float d = o - mu;
    float var = d * d;
    #pragma unroll
    for (int off = 16; off > 0; off >>= 1) var += __shfl_xor_sync(0xffffffffu, var, off);
    var *= (1.0f / 32.0f);

    float yv = d * rsqrtf(var + 1e-5f) * sB[32 + j] + sB[64 + j];
    out[(long long)n * 32 + j] = yv / (1.0f + __expf(-yv));   // SiLU
}

// ---------------- launch ----------------
extern "C" void kernel_launch(void* const* d_in, const int* in_sizes, int n_in,
                              void* d_out, int out_size) {
    const float* pos   = (const float*)d_in[0];
    const void*  eidx  = d_in[1];
    const float* Wq    = (const float*)d_in[2];
    const float* bq    = (const float*)d_in[3];
    const float* Wk    = (const float*)d_in[4];
    const float* bk    = (const float*)d_in[5];
    const float* Wv    = (const float*)d_in[6];
    const float* bv    = (const float*)d_in[7];
    const float* Wout  = (const float*)d_in[8];
    const float* bout  = (const float*)d_in[9];
    const float* gamma = (const float*)d_in[10];
    const float* beta  = (const float*)d_in[11];

    int N = in_sizes[0] / 3;      // 100000
    int E = in_sizes[1] / 2;      // 500000
    if (N > N_NODES_MAX) N = N_NODES_MAX;

    setup_kernel<<<(N + 383) / 384, 384>>>(pos, eidx, Wq, bq, Wk, bk, Wv, bv, Wout, N);
    edge_kernel<<<(E + 256 * EPT - 1) / (256 * EPT), 256>>>(eidx, E);
    node_kernel<<<(N + 7) / 8, 256>>>((float*)d_out, bout, gamma, beta, N);
}

// round 14
// speedup vs baseline: 1.5501x; 1.0150x over previous
#include <cuda_runtime.h>
#include <cuda_bf16.h>

// EquivariantLayer: edge attention (4 heads), scatter-mean, out-proj, LN, SiLU.
// R14: single change vs R12 — edge kernel EPT 4->8 with all 16 position
// gathers batched before compute (discriminating test: gather-latency-bound
// vs reduction/L1tex-bound). Setup/node identical to R12 (node re-zeroes
// g_acc so no explicit zeroing pass is needed; deterministic every call).

#define N_NODES_MAX 100000
#define HEADS 4
#define HIDDEN 32
#define PROJ 128
#define EPT 8   // edges per thread

// ---------------- device scratch (no allocations allowed) ----------------
__device__ float4 g_acc[N_NODES_MAX * HEADS];   // {attn_sum, S.x, S.y, S.z}; zero at load
__device__ float4 g_pos4[N_NODES_MAX];          // packed positions {x,y,z,0}

struct Pre {
    float G[HEADS][3][3];    // (Wq_h Wk_h^T)/sqrt(32)            36 floats
    float u[HEADS][3];       // (Wq_h bk_h + Wk_h bq_h)/sqrt(32)  12
    float c[HEADS];          // (bq_h . bk_h)/sqrt(32)             4
    float M[HEADS][3][32];   // Wv[c, h-slice] @ Wout[h-slice, j] 384
    float Bw[HEADS][32];     // bv[h-slice] @ Wout[h-slice, j]    128
};
__device__ Pre g_pre;        // 564 floats: G | u | c | M | Bw
__device__ int g_is64;

// ---------------- 1) setup: detect + precompute + pos-pack ----------------
__global__ void __launch_bounds__(384) setup_kernel(
        const float* __restrict__ pos, const void* __restrict__ eidx,
        const float* __restrict__ Wq, const float* __restrict__ bq,
        const float* __restrict__ Wk, const float* __restrict__ bk,
        const float* __restrict__ Wv, const float* __restrict__ bv,
        const float* __restrict__ Wout, int N) {
    int g = blockIdx.x * 384 + threadIdx.x;
    if (g < N)
        g_pos4[g] = make_float4(pos[3 * g + 0], pos[3 * g + 1], pos[3 * g + 2], 0.f);

    if (blockIdx.x != 0) return;
    int t = threadIdx.x;

    // dtype detect (warp 0): int64 values in [0,1e5) -> every hi-word zero
    if (t < 32) {
        const unsigned int* p = (const unsigned int*)eidx;
        bool hz = (p[2 * t + 1] == 0u);
        unsigned int mask = __ballot_sync(0xffffffffu, hz);
        if (t == 0) g_is64 = (mask == 0xffffffffu) ? 1 : 0;
    }

    const float SCALE = 0.17677669529663687f;  // 1/sqrt(32)
    {   // M[h][c][j], 384 threads, full unroll for MLP
        int h = t / 96, rem = t % 96, cd = rem / 32, j = rem % 32;
        float s = 0.f;
        #pragma unroll
        for (int d = 0; d < 32; d++)
            s += Wv[cd * PROJ + h * 32 + d] * Wout[(h * 32 + d) * 32 + j];
        g_pre.M[h][cd][j] = s;
    }
    if (t < 128) {  // Bw[h][j]
        int h = t / 32, j = t % 32;
        float s = 0.f;
        #pragma unroll
        for (int d = 0; d < 32; d++)
            s += bv[h * 32 + d] * Wout[(h * 32 + d) * 32 + j];
        g_pre.Bw[h][j] = s;
    }
    if (t < 36) {   // G[h][a][b]
        int h = t / 9, rem = t % 9, a = rem / 3, b = rem % 3;
        float s = 0.f;
        #pragma unroll
        for (int d = 0; d < 32; d++)
            s += Wq[a * PROJ + h * 32 + d] * Wk[b * PROJ + h * 32 + d];
        g_pre.G[h][a][b] = s * SCALE;
    }
    if (t < 12) {   // u[h][a]
        int h = t / 3, a = t % 3;
        float s = 0.f;
        #pragma unroll
        for (int d = 0; d < 32; d++)
            s += Wq[a * PROJ + h * 32 + d] * bk[h * 32 + d]
               + Wk[a * PROJ + h * 32 + d] * bq[h * 32 + d];
        g_pre.u[h][a] = s * SCALE;
    }
    if (t < 4) {    // c[h]
        float s = 0.f;
        #pragma unroll
        for (int d = 0; d < 32; d++)
            s += bq[t * 32 + d] * bk[t * 32 + d];
        g_pre.c[t] = s * SCALE;
    }
}

// ---------------- 2) per-edge: scores -> softmax -> red.v4 scatter ----------
__device__ __forceinline__ void edge_body(const float* sP, int c, float x, float y, float z) {
    float s[HEADS];
    float m = -1e30f;
    #pragma unroll
    for (int h = 0; h < HEADS; h++) {
        const float* G = &sP[h * 9];
        float gx = G[0] * x + G[1] * y + G[2] * z;
        float gy = G[3] * x + G[4] * y + G[5] * z;
        float gz = G[6] * x + G[7] * y + G[8] * z;
        float v = x * gx + y * gy + z * gz
                + sP[36 + h * 3 + 0] * x + sP[36 + h * 3 + 1] * y + sP[36 + h * 3 + 2] * z
                + sP[48 + h];
        s[h] = v;
        m = fmaxf(m, v);
    }
    float tsum = 0.f;
    #pragma unroll
    for (int h = 0; h < HEADS; h++) { s[h] = __expf(s[h] - m); tsum += s[h]; }
    float inv = 1.0f / tsum;

    float4* base = &g_acc[(long long)c * HEADS];
    #pragma unroll
    for (int h = 0; h < HEADS; h++) {
        float a = s[h] * inv;
        float4* p = base + h;
        asm volatile("red.global.add.v4.f32 [%0], {%1, %2, %3, %4};"
                     :: "l"(p), "f"(a), "f"(a * x), "f"(a * y), "f"(a * z)
                     : "memory");
    }
}

__global__ void __launch_bounds__(256) edge_kernel(const void* __restrict__ eidx, int E) {
    __shared__ float sP[52];  // [0:36) G, [36:48) u, [48:52) c
    int t = threadIdx.x;
    if (t < 52) sP[t] = ((const float*)&g_pre)[t];
    __syncthreads();

    int e0 = (blockIdx.x * 256 + t) * EPT;
    if (e0 >= E) return;
    int is64 = g_is64;
    int nleft = E - e0;

    if (nleft >= EPT) {
        int r[EPT], c[EPT];
        if (is64) {
            const long long* p = (const long long*)eidx;
            if (((unsigned)E & 1u) == 0u) {   // e0 is always even
                #pragma unroll
                for (int i = 0; i < EPT / 2; i++) {
                    longlong2 A = *(const longlong2*)(p + e0 + 2 * i);
                    r[2 * i] = (int)A.x; r[2 * i + 1] = (int)A.y;
                }
                #pragma unroll
                for (int i = 0; i < EPT / 2; i++) {
                    longlong2 C = *(const longlong2*)(p + E + e0 + 2 * i);
                    c[2 * i] = (int)C.x; c[2 * i + 1] = (int)C.y;
                }
            } else {
                #pragma unroll
                for (int i = 0; i < EPT; i++) {
                    r[i] = (int)p[e0 + i];
                    c[i] = (int)p[(long long)E + e0 + i];
                }
            }
        } else {
            const int* p = (const int*)eidx;
            if (((unsigned)E & 3u) == 0u) {   // e0 is a multiple of 4 (EPT=8)
                #pragma unroll
                for (int i = 0; i < EPT / 4; i++) {
                    int4 A = *(const int4*)(p + e0 + 4 * i);
                    r[4 * i] = A.x; r[4 * i + 1] = A.y; r[4 * i + 2] = A.z; r[4 * i + 3] = A.w;
                }
                #pragma unroll
                for (int i = 0; i < EPT / 4; i++) {
                    int4 C = *(const int4*)(p + E + e0 + 4 * i);
                    c[4 * i] = C.x; c[4 * i + 1] = C.y; c[4 * i + 2] = C.z; c[4 * i + 3] = C.w;
                }
            } else {
                #pragma unroll
                for (int i = 0; i < EPT; i++) { r[i] = p[e0 + i]; c[i] = p[E + e0 + i]; }
            }
        }

        // batch all 16 gathers for maximum MLP before any compute
        float4 Pr[EPT], Pc[EPT];
        #pragma unroll
        for (int i = 0; i < EPT; i++) Pr[i] = __ldg(&g_pos4[r[i]]);
        #pragma unroll
        for (int i = 0; i < EPT; i++) Pc[i] = __ldg(&g_pos4[c[i]]);

        #pragma unroll
        for (int i = 0; i < EPT; i++)
            edge_body(sP, c[i], Pr[i].x - Pc[i].x, Pr[i].y - Pc[i].y, Pr[i].z - Pc[i].z);
    } else {
        for (int i = 0; i < nleft; i++) {
            int r, c;
            if (is64) {
                const long long* p = (const long long*)eidx;
                r = (int)p[e0 + i];
                c = (int)p[(long long)E + e0 + i];
            } else {
                const int* p = (const int*)eidx;
                r = p[e0 + i];
                c = p[E + e0 + i];
            }
            float4 Pr = __ldg(&g_pos4[r]);
            float4 Pc = __ldg(&g_pos4[c]);
            edge_body(sP, c, Pr.x - Pc.x, Pr.y - Pc.y, Pr.z - Pc.z);
        }
    }
}

// ---------------- 3) per-node: reconstruct, project, LN, SiLU, re-zero ------
__global__ void __launch_bounds__(256) node_kernel(float* __restrict__ out,
                                                   const float* __restrict__ bout,
                                                   const float* __restrict__ gamma,
                                                   const float* __restrict__ beta, int N) {
    __shared__ float sM[512];   // M (384) then Bw (128)
    __shared__ float sB[96];    // bout | gamma | beta
    const float* src = ((const float*)&g_pre) + 52;
    for (int i = threadIdx.x; i < 512; i += blockDim.x) sM[i] = src[i];
    if (threadIdx.x < 32) {
        sB[threadIdx.x]      = bout[threadIdx.x];
        sB[32 + threadIdx.x] = gamma[threadIdx.x];
        sB[64 + threadIdx.x] = beta[threadIdx.x];
    }
    __syncthreads();

    int n = (blockIdx.x * blockDim.x + threadIdx.x) >> 5;
    int j = threadIdx.x & 31;
    if (n >= N) return;

    float4 a0 = g_acc[n * 4 + 0];
    float4 a1 = g_acc[n * 4 + 1];
    float4 a2 = g_acc[n * 4 + 2];
    float4 a3 = g_acc[n * 4 + 3];

    // re-zero for the next kernel_launch call (lanes 0..3 of this warp cover
    // the node's 4 float4 slots; values already in registers above)
    if (j < 4) g_acc[n * 4 + j] = make_float4(0.f, 0.f, 0.f, 0.f);

    float cnt = a0.x + a1.x + a2.x + a3.x;   // == edge count (softmax sums to 1)
    float inv = 1.0f / fmaxf(cnt, 1.0f);

    float acc =
        a0.y * sM[  0 + j] + a0.z * sM[ 32 + j] + a0.w * sM[ 64 + j] + a0.x * sM[384 + j] +
        a1.y * sM[ 96 + j] + a1.z * sM[128 + j] + a1.w * sM[160 + j] + a1.x * sM[416 + j] +
        a2.y * sM[192 + j] + a2.z * sM[224 + j] + a2.w * sM[256 + j] + a2.x * sM[448 + j] +
        a3.y * sM[288 + j] + a3.z * sM[320 + j] + a3.w * sM[352 + j] + a3.x * sM[480 + j];

    float o = acc * inv + sB[j];

    float mu = o;
    #pragma unroll
    for (int off = 16; off > 0; off >>= 1) mu += __shfl_xor_sync(0xffffffffu, mu, off);
    mu *= (1.0f / 32.0f);
    float d = o - mu;
    float var = d * d;
    #pragma unroll
    for (int off = 16; off > 0; off >>= 1) var += __shfl_xor_sync(0xffffffffu, var, off);
    var *= (1.0f / 32.0f);

    float yv = d * rsqrtf(var + 1e-5f) * sB[32 + j] + sB[64 + j];
    out[(long long)n * 32 + j] = yv / (1.0f + __expf(-yv));   // SiLU
}

// ---------------- launch ----------------
extern "C" void kernel_launch(void* const* d_in, const int* in_sizes, int n_in,
                              void* d_out, int out_size) {
    const float* pos   = (const float*)d_in[0];
    const void*  eidx  = d_in[1];
    const float* Wq    = (const float*)d_in[2];
    const float* bq    = (const float*)d_in[3];
    const float* Wk    = (const float*)d_in[4];
    const float* bk    = (const float*)d_in[5];
    const float* Wv    = (const float*)d_in[6];
    const float* bv    = (const float*)d_in[7];
    const float* Wout  = (const float*)d_in[8];
    const float* bout  = (const float*)d_in[9];
    const float* gamma = (const float*)d_in[10];
    const float* beta  = (const float*)d_in[11];

    int N = in_sizes[0] / 3;      // 100000
    int E = in_sizes[1] / 2;      // 500000
    if (N > N_NODES_MAX) N = N_NODES_MAX;

    setup_kernel<<<(N + 383) / 384, 384>>>(pos, eidx, Wq, bq, Wk, bk, Wv, bv, Wout, N);
    edge_kernel<<<(E + 256 * EPT - 1) / (256 * EPT), 256>>>(eidx, E);
    node_kernel<<<(N + 7) / 8, 256>>>((float*)d_out, bout, gamma, beta, N);
}

// round 16
// speedup vs baseline: 1.5936x; 1.0281x over previous
#include <cuda_runtime.h>
#include <cuda_bf16.h>

// EquivariantLayer: edge attention (4 heads), scatter-mean, out-proj, LN, SiLU.
// R15: edge kernel restructured for coalesced reductions. Payloads staged in
// SMEM; reduction phase maps lane 4m+h -> (edge m, head h) so each red.v4
// warp-instruction writes groups of 4 lanes into ONE contiguous 64B region
// (8 lines/instr instead of 32) — 4x fewer L1tex wavefronts on the red
// stream, the modeled edge bottleneck. Setup/node identical to R14.

#define N_NODES_MAX 100000
#define HEADS 4
#define HIDDEN 32
#define PROJ 128
#define EDGES_PER_BLOCK 1024   // 256 threads x 4 edges

// ---------------- device scratch (no allocations allowed) ----------------
__device__ float4 g_acc[N_NODES_MAX * HEADS];   // {attn_sum, S.x, S.y, S.z}; zero at load
__device__ float4 g_pos4[N_NODES_MAX];          // packed positions {x,y,z,0}

struct Pre {
    float G[HEADS][3][3];    // (Wq_h Wk_h^T)/sqrt(32)            36 floats
    float u[HEADS][3];       // (Wq_h bk_h + Wk_h bq_h)/sqrt(32)  12
    float c[HEADS];          // (bq_h . bk_h)/sqrt(32)             4
    float M[HEADS][3][32];   // Wv[c, h-slice] @ Wout[h-slice, j] 384
    float Bw[HEADS][32];     // bv[h-slice] @ Wout[h-slice, j]    128
};
__device__ Pre g_pre;        // 564 floats: G | u | c | M | Bw
__device__ int g_is64;

// ---------------- 1) setup: detect + precompute + pos-pack ----------------
__global__ void __launch_bounds__(384) setup_kernel(
        const float* __restrict__ pos, const void* __restrict__ eidx,
        const float* __restrict__ Wq, const float* __restrict__ bq,
        const float* __restrict__ Wk, const float* __restrict__ bk,
        const float* __restrict__ Wv, const float* __restrict__ bv,
        const float* __restrict__ Wout, int N) {
    int g = blockIdx.x * 384 + threadIdx.x;
    if (g < N)
        g_pos4[g] = make_float4(pos[3 * g + 0], pos[3 * g + 1], pos[3 * g + 2], 0.f);

    if (blockIdx.x != 0) return;
    int t = threadIdx.x;

    // dtype detect (warp 0): int64 values in [0,1e5) -> every hi-word zero
    if (t < 32) {
        const unsigned int* p = (const unsigned int*)eidx;
        bool hz = (p[2 * t + 1] == 0u);
        unsigned int mask = __ballot_sync(0xffffffffu, hz);
        if (t == 0) g_is64 = (mask == 0xffffffffu) ? 1 : 0;
    }

    const float SCALE = 0.17677669529663687f;  // 1/sqrt(32)
    {   // M[h][c][j], 384 threads, full unroll for MLP
        int h = t / 96, rem = t % 96, cd = rem / 32, j = rem % 32;
        float s = 0.f;
        #pragma unroll
        for (int d = 0; d < 32; d++)
            s += Wv[cd * PROJ + h * 32 + d] * Wout[(h * 32 + d) * 32 + j];
        g_pre.M[h][cd][j] = s;
    }
    if (t < 128) {  // Bw[h][j]
        int h = t / 32, j = t % 32;
        float s = 0.f;
        #pragma unroll
        for (int d = 0; d < 32; d++)
            s += bv[h * 32 + d] * Wout[(h * 32 + d) * 32 + j];
        g_pre.Bw[h][j] = s;
    }
    if (t < 36) {   // G[h][a][b]
        int h = t / 9, rem = t % 9, a = rem / 3, b = rem % 3;
        float s = 0.f;
        #pragma unroll
        for (int d = 0; d < 32; d++)
            s += Wq[a * PROJ + h * 32 + d] * Wk[b * PROJ + h * 32 + d];
        g_pre.G[h][a][b] = s * SCALE;
    }
    if (t < 12) {   // u[h][a]
        int h = t / 3, a = t % 3;
        float s = 0.f;
        #pragma unroll
        for (int d = 0; d < 32; d++)
            s += Wq[a * PROJ + h * 32 + d] * bk[h * 32 + d]
               + Wk[a * PROJ + h * 32 + d] * bq[h * 32 + d];
        g_pre.u[h][a] = s * SCALE;
    }
    if (t < 4) {    // c[h]
        float s = 0.f;
        #pragma unroll
        for (int d = 0; d < 32; d++)
            s += bq[t * 32 + d] * bk[t * 32 + d];
        g_pre.c[t] = s * SCALE;
    }
}

// ---------------- 2) per-edge: staged softmax payload, coalesced red --------
// SMEM payload per edge slot (stride 9 floats, conflict-free):
//   [0..3] a0..a3 (softmax weights), [4..6] x,y,z, [7,8] pad
__global__ void __launch_bounds__(256) edge_kernel(const void* __restrict__ eidx, int E) {
    __shared__ float sP[52];                       // G | u | c
    __shared__ int   sC[EDGES_PER_BLOCK];          // destination node per slot
    __shared__ float sD[EDGES_PER_BLOCK * 9];      // payload, stride 9

    int t = threadIdx.x;
    if (t < 52) sP[t] = ((const float*)&g_pre)[t];
    __syncthreads();

    int base = blockIdx.x * EDGES_PER_BLOCK;
    int nEdges = E - base;
    if (nEdges > EDGES_PER_BLOCK) nEdges = EDGES_PER_BLOCK;
    int is64 = g_is64;

    // ---- phase 1: indices (coalesced per-lane), gathers (batched), payload ----
    int rr[4], cc[4];
    bool valid[4];
    #pragma unroll
    for (int k = 0; k < 4; k++) {
        int slot = t + 256 * k;
        valid[k] = (slot < nEdges);
        if (valid[k]) {
            int e = base + slot;
            if (is64) {
                const long long* p = (const long long*)eidx;
                rr[k] = (int)p[e];
                cc[k] = (int)p[(long long)E + e];
            } else {
                const int* p = (const int*)eidx;
                rr[k] = p[e];
                cc[k] = p[E + e];
            }
        }
    }

    float4 Pr[4], Pc[4];
    #pragma unroll
    for (int k = 0; k < 4; k++) if (valid[k]) Pr[k] = __ldg(&g_pos4[rr[k]]);
    #pragma unroll
    for (int k = 0; k < 4; k++) if (valid[k]) Pc[k] = __ldg(&g_pos4[cc[k]]);

    #pragma unroll
    for (int k = 0; k < 4; k++) {
        if (!valid[k]) continue;
        float x = Pr[k].x - Pc[k].x;
        float y = Pr[k].y - Pc[k].y;
        float z = Pr[k].z - Pc[k].z;

        float s[HEADS];
        float m = -1e30f;
        #pragma unroll
        for (int h = 0; h < HEADS; h++) {
            const float* G = &sP[h * 9];
            float gx = G[0] * x + G[1] * y + G[2] * z;
            float gy = G[3] * x + G[4] * y + G[5] * z;
            float gz = G[6] * x + G[7] * y + G[8] * z;
            float v = x * gx + y * gy + z * gz
                    + sP[36 + h * 3 + 0] * x + sP[36 + h * 3 + 1] * y + sP[36 + h * 3 + 2] * z
                    + sP[48 + h];
            s[h] = v;
            m = fmaxf(m, v);
        }
        float tsum = 0.f;
        #pragma unroll
        for (int h = 0; h < HEADS; h++) { s[h] = __expf(s[h] - m); tsum += s[h]; }
        float inv = 1.0f / tsum;

        int slot = t + 256 * k;
        float* d = &sD[slot * 9];
        d[0] = s[0] * inv;
        d[1] = s[1] * inv;
        d[2] = s[2] * inv;
        d[3] = s[3] * inv;
        d[4] = x; d[5] = y; d[6] = z;
        sC[slot] = cc[k];
    }
    __syncthreads();

    // ---- phase 2: coalesced reductions. pair p=(slot,head); lanes 4m..4m+3
    // share a slot -> red.v4 hits one contiguous 64B region per edge. ----
    int nPairs = nEdges * 4;
    for (int p = t; p < nPairs; p += 256) {
        int slot = p >> 2;
        int h = p & 3;
        int c = sC[slot];
        const float* d = &sD[slot * 9];
        float a = d[h];
        float x = d[4], y = d[5], z = d[6];
        float4* dst = &g_acc[(long long)c * HEADS + h];
        asm volatile("red.global.add.v4.f32 [%0], {%1, %2, %3, %4};"
                     :: "l"(dst), "f"(a), "f"(a * x), "f"(a * y), "f"(a * z)
                     : "memory");
    }
}

// ---------------- 3) per-node: reconstruct, project, LN, SiLU, re-zero ------
__global__ void __launch_bounds__(256) node_kernel(float* __restrict__ out,
                                                   const float* __restrict__ bout,
                                                   const float* __restrict__ gamma,
                                                   const float* __restrict__ beta, int N) {
    __shared__ float sM[512];   // M (384) then Bw (128)
    __shared__ float sB[96];    // bout | gamma | beta
    const float* src = ((const float*)&g_pre) + 52;
    for (int i = threadIdx.x; i < 512; i += blockDim.x) sM[i] = src[i];
    if (threadIdx.x < 32) {
        sB[threadIdx.x]      = bout[threadIdx.x];
        sB[32 + threadIdx.x] = gamma[threadIdx.x];
        sB[64 + threadIdx.x] = beta[threadIdx.x];
    }
    __syncthreads();

    int n = (blockIdx.x * blockDim.x + threadIdx.x) >> 5;
    int j = threadIdx.x & 31;
    if (n >= N) return;

    float4 a0 = g_acc[n * 4 + 0];
    float4 a1 = g_acc[n * 4 + 1];
    float4 a2 = g_acc[n * 4 + 2];
    float4 a3 = g_acc[n * 4 + 3];

    // re-zero for the next kernel_launch call (lanes 0..3 of this warp cover
    // the node's 4 float4 slots; values already in registers above)
    if (j < 4) g_acc[n * 4 + j] = make_float4(0.f, 0.f, 0.f, 0.f);

    float cnt = a0.x + a1.x + a2.x + a3.x;   // == edge count (softmax sums to 1)
    float inv = 1.0f / fmaxf(cnt, 1.0f);

    float acc =
        a0.y * sM[  0 + j] + a0.z * sM[ 32 + j] + a0.w * sM[ 64 + j] + a0.x * sM[384 + j] +
        a1.y * sM[ 96 + j] + a1.z * sM[128 + j] + a1.w * sM[160 + j] + a1.x * sM[416 + j] +
        a2.y * sM[192 + j] + a2.z * sM[224 + j] + a2.w * sM[256 + j] + a2.x * sM[448 + j] +
        a3.y * sM[288 + j] + a3.z * sM[320 + j] + a3.w * sM[352 + j] + a3.x * sM[480 + j];

    float o = acc * inv + sB[j];

    float mu = o;
    #pragma unroll
    for (int off = 16; off > 0; off >>= 1) mu += __shfl_xor_sync(0xffffffffu, mu, off);
    mu *= (1.0f / 32.0f);
    float d = o - mu;
    float var = d * d;
    #pragma unroll
    for (int off = 16; off > 0; off >>= 1) var += __shfl_xor_sync(0xffffffffu, var, off);
    var *= (1.0f / 32.0f);

    float yv = d * rsqrtf(var + 1e-5f) * sB[32 + j] + sB[64 + j];
    out[(long long)n * 32 + j] = yv / (1.0f + __expf(-yv));   // SiLU
}

// ---------------- launch ----------------
extern "C" void kernel_launch(void* const* d_in, const int* in_sizes, int n_in,
                              void* d_out, int out_size) {
    const float* pos   = (const float*)d_in[0];
    const void*  eidx  = d_in[1];
    const float* Wq    = (const float*)d_in[2];
    const float* bq    = (const float*)d_in[3];
    const float* Wk    = (const float*)d_in[4];
    const float* bk    = (const float*)d_in[5];
    const float* Wv    = (const float*)d_in[6];
    const float* bv    = (const float*)d_in[7];
    const float* Wout  = (const float*)d_in[8];
    const float* bout  = (const float*)d_in[9];
    const float* gamma = (const float*)d_in[10];
    const float* beta  = (const float*)d_in[11];

    int N = in_sizes[0] / 3;      // 100000
    int E = in_sizes[1] / 2;      // 500000
    if (N > N_NODES_MAX) N = N_NODES_MAX;

    setup_kernel<<<(N + 383) / 384, 384>>>(pos, eidx, Wq, bq, Wk, bk, Wv, bv, Wout, N);
    edge_kernel<<<(E + EDGES_PER_BLOCK - 1) / EDGES_PER_BLOCK, 256>>>(eidx, E);
    node_kernel<<<(N + 7) / 8, 256>>>((float*)d_out, bout, gamma, beta, N);
}